// round 2
// baseline (speedup 1.0000x reference)
#include <cuda_runtime.h>

#define N_NODES 100000
#define N_EDGES 3200000
#define SLOTS   128
#define FULL    0xffffffffu

// ---------------- static scratch (zero-initialized at load; self-cleaning) ----
__device__ int    g_cnt  [N_NODES];           // reset by k_agg
__device__ int    g_slots[N_NODES * SLOTS];   // CSR-by-dst: src indices
__device__ float  g_dinv [N_NODES];
__device__ float  g_xd   [N_NODES];           // dinv[n] * x[n]
__device__ float  g_s1   [N_NODES];           // scalar layer-1 aggregate
__device__ float  g_csum [N_NODES];           // reset by k_mlp
__device__ float  g_cw   [N_NODES];           // dinv[n]*(csum[n]+dinv[n])
__device__ float  g_h2g  [N_NODES * 32];      // dinv[n] * (a1(n) @ W2)
__device__ double g_accY [32];                // reset by k_final

// ---------------- kernel B: histogram + slot scatter (CSR build), int4 ---------
__global__ void k_scatter(const int4* __restrict__ s4, const int4* __restrict__ d4) {
    int i = blockIdx.x * blockDim.x + threadIdx.x;
    if (i >= N_EDGES / 4) return;
    int4 s = __ldg(s4 + i);
    int4 d = __ldg(d4 + i);
    int p;
    p = atomicAdd(g_cnt + d.x, 1); if (p < SLOTS) g_slots[d.x * SLOTS + p] = s.x;
    p = atomicAdd(g_cnt + d.y, 1); if (p < SLOTS) g_slots[d.y * SLOTS + p] = s.y;
    p = atomicAdd(g_cnt + d.z, 1); if (p < SLOTS) g_slots[d.z * SLOTS + p] = s.z;
    p = atomicAdd(g_cnt + d.w, 1); if (p < SLOTS) g_slots[d.w * SLOTS + p] = s.w;
}

// ---------------- kernel C: dinv + xd ------------------------------------------
__global__ void k_node_init(const float* __restrict__ x) {
    int n = blockIdx.x * blockDim.x + threadIdx.x;
    if (n >= N_NODES) return;
    float di = rsqrtf((float)(g_cnt[n] + 1));   // +1 self loop
    g_dinv[n] = di;
    g_xd[n]   = di * x[n];
}

// ---------------- kernel D: warp-per-node scalar gather (s1) + csum atomics ----
__global__ void k_s1_csum() {
    int t = blockIdx.x * blockDim.x + threadIdx.x;
    int n = t >> 5;
    int lane = t & 31;
    if (n >= N_NODES) return;
    int cnt = g_cnt[n]; if (cnt > SLOTS) cnt = SLOTS;
    float du = g_dinv[n];
    const int* __restrict__ row = g_slots + n * SLOTS;
    float acc = 0.f;
    for (int e = lane; e < cnt; e += 32) {
        int s = __ldg(row + e);
        acc += g_xd[s];
        atomicAdd(&g_csum[s], du);            // one per original edge
    }
    #pragma unroll
    for (int o = 16; o; o >>= 1) acc += __shfl_down_sync(FULL, acc, o);
    if (lane == 0) g_s1[n] = du * (acc + g_xd[n]);   // + self-loop term
}

// ---------------- kernel E: per-node MLP via fma.rn.f32x2 -----------------------
// h2g[n] = dinv[n] * (lrelu(s1*W1+b1, 0.1) @ W2);  cw[n] = dinv*(csum+dinv)
__global__ void k_mlp(const float* __restrict__ W1, const float* __restrict__ b1,
                      const float* __restrict__ W2) {
    __shared__ float sW1[64], sb1[64];
    __shared__ __align__(16) float sW2[64 * 32];
    int t = threadIdx.x;
    if (t < 64) { sW1[t] = W1[t]; sb1[t] = b1[t]; }
    for (int i = t; i < 64 * 32; i += blockDim.x) sW2[i] = W2[i];
    __syncthreads();

    int n = blockIdx.x * blockDim.x + t;
    if (n >= N_NODES) return;
    float s1 = g_s1[n];
    float di = g_dinv[n];

    unsigned long long acc[16];
    #pragma unroll
    for (int j = 0; j < 16; j++) acc[j] = 0ull;

    #pragma unroll 4
    for (int c = 0; c < 64; c++) {
        float a = fmaf(s1, sW1[c], sb1[c]);
        a = a > 0.f ? a : 0.1f * a;           // leaky_relu(0.1)
        unsigned int au = __float_as_uint(a);
        unsigned long long a2;
        asm("mov.b64 %0, {%1, %1};" : "=l"(a2) : "r"(au));
        const unsigned long long* w = (const unsigned long long*)(sW2 + c * 32);
        #pragma unroll
        for (int j = 0; j < 16; j++)
            asm("fma.rn.f32x2 %0, %1, %2, %0;" : "+l"(acc[j]) : "l"(a2), "l"(w[j]));
    }

    unsigned int diu = __float_as_uint(di);
    unsigned long long d2;
    asm("mov.b64 %0, {%1, %1};" : "=l"(d2) : "r"(diu));
    unsigned long long* out = (unsigned long long*)(g_h2g + n * 32);
    #pragma unroll
    for (int j = 0; j < 16; j++) {
        unsigned long long r;
        asm("mul.rn.f32x2 %0, %1, %2;" : "=l"(r) : "l"(acc[j]), "l"(d2));
        out[j] = r;
    }

    float cs = g_csum[n];
    g_csum[n] = 0.f;                          // self-clean for next replay
    g_cw[n] = di * (cs + di);
}

// ---------------- kernel F: layer-2 gather + lrelu + weighted Y accumulation ----
// Y[f] = sum_n cw[n] * lrelu(du*agg[f] + b2[f]);  W3 applied once in k_final.
__global__ void k_agg(const float* __restrict__ b2) {
    __shared__ double sY[32];
    int t = threadIdx.x, lane = t & 31;
    if (t < 32) sY[t] = 0.0;
    __syncthreads();

    float b2l = b2[lane];
    double y = 0.0;
    int wid = blockIdx.x * (blockDim.x >> 5) + (t >> 5);
    int nw  = gridDim.x * (blockDim.x >> 5);

    for (int n = wid; n < N_NODES; n += nw) {
        int cnt = 0;
        if (lane == 0) { cnt = g_cnt[n]; g_cnt[n] = 0; }   // read + self-clean
        cnt = __shfl_sync(FULL, cnt, 0);
        int c = cnt < SLOTS ? cnt : SLOTS;
        float du = g_dinv[n];
        const int* __restrict__ row = g_slots + n * SLOTS;
        float acc = g_h2g[n * 32 + lane];     // self-loop term

        int e = 0;
        for (; e + 4 <= c; e += 4) {
            int s0 = __ldg(row + e),     s1 = __ldg(row + e + 1);
            int s2 = __ldg(row + e + 2), s3 = __ldg(row + e + 3);
            float v0 = __ldg(g_h2g + s0 * 32 + lane);
            float v1 = __ldg(g_h2g + s1 * 32 + lane);
            float v2 = __ldg(g_h2g + s2 * 32 + lane);
            float v3 = __ldg(g_h2g + s3 * 32 + lane);
            acc += (v0 + v1) + (v2 + v3);
        }
        for (; e < c; e++)
            acc += __ldg(g_h2g + __ldg(row + e) * 32 + lane);

        float v  = fmaf(acc, du, b2l);
        float a2 = v > 0.f ? v : 0.1f * v;    // leaky_relu(0.1)
        y += (double)(g_cw[n] * a2);
    }

    atomicAdd(&sY[lane], y);                  // 8 warps -> 32 slots
    __syncthreads();
    if (t < 32) atomicAdd(&g_accY[t], sY[t]); // 512 blocks per address
}

// ---------------- kernel G: finalize  out[j] = (Y @ W3)/N + b3 ------------------
__global__ void k_final(const float* __restrict__ W3, const float* __restrict__ b3,
                        float* __restrict__ out) {
    __shared__ double sY[32];
    int t = threadIdx.x;                      // 32 threads
    sY[t] = g_accY[t];
    __syncwarp();
    if (t < 10) {
        double s = 0.0;
        #pragma unroll
        for (int f = 0; f < 32; f++) s += sY[f] * (double)W3[f * 10 + t];
        out[t] = (float)(s * (1.0 / (double)N_NODES)) + b3[t];
    }
    g_accY[t] = 0.0;                          // self-clean for next replay
}

// ---------------- launch ---------------------------------------------------------
extern "C" void kernel_launch(void* const* d_in, const int* in_sizes, int n_in,
                              void* d_out, int out_size) {
    const float* x   = (const float*)d_in[0];
    const int*   ei  = (const int*)  d_in[1];   // [2, E] row-major
    const float* W1  = (const float*)d_in[2];
    const float* b1  = (const float*)d_in[3];
    const float* W2  = (const float*)d_in[4];
    const float* b2  = (const float*)d_in[5];
    const float* W3  = (const float*)d_in[6];
    const float* b3  = (const float*)d_in[7];
    float* out = (float*)d_out;

    const int4* src4 = (const int4*)ei;
    const int4* dst4 = (const int4*)(ei + N_EDGES);

    k_scatter  <<<(N_EDGES / 4 + 255) / 256, 256>>>(src4, dst4);
    k_node_init<<<(N_NODES + 255) / 256, 256>>>(x);
    k_s1_csum  <<<(N_NODES * 32 + 255) / 256, 256>>>();
    k_mlp      <<<(N_NODES + 255) / 256, 256>>>(W1, b1, W2);
    k_agg      <<<512, 256>>>(b2);
    k_final    <<<1, 32>>>(W3, b3, out);
}